// round 13
// baseline (speedup 1.0000x reference)
#include <cuda_runtime.h>
#include <cuda_fp16.h>
#include <math.h>

#define NMAX 50000
#define DDIM 64

// fp16 copy of transformed features (gather side of the scatter)
__device__ __half g_hh[(size_t)NMAX * DDIM];

// packed f32x2 FMA (FFMA2) — PTX-only; identical fp32 numerics.
#define FMA_F32X2(acc, a, b) \
    asm("fma.rn.f32x2 %0, %1, %2, %0;" : "+l"(acc) : "l"(a), "l"(b))
#define PACK_F32X2(out, lo, hi) \
    asm("mov.b64 %0, {%1, %2};" : "=l"(out) : "r"(lo), "r"(hi))
#define UNPACK_F32X2(lo, hi, in) \
    asm("mov.b64 {%0, %1}, %2;" : "=r"(lo), "=r"(hi) : "l"(in))

// ---------------------------------------------------------------------------
// Kernel 1: h = X @ W^T ; out = h*skip + bias (fp32) ; g_hh = h (fp16)
// 128 rows x 64 cols per block, 8x4 register tile, f32x2 accumulation.
// (R12 verbatim — measured 16.6us.)
// ---------------------------------------------------------------------------
#define XSTR 132
#define WSTR 68

__global__ void __launch_bounds__(256) gemm_skip_kernel(
    const float* __restrict__ X, const float* __restrict__ W,
    const float* __restrict__ bias, const float* __restrict__ skipw,
    float* __restrict__ out, int n)
{
    __shared__ float sW[DDIM * WSTR];   // sW[d*WSTR + o] = W[o][d]
    __shared__ float sX[DDIM * XSTR];   // sX[d*XSTR + r]

    const int tid  = threadIdx.x;
    const int row0 = blockIdx.x * 128;

    #pragma unroll
    for (int i = 0; i < 16; i++) {
        int idx = tid + i * 256;
        int o = idx >> 6, d = idx & 63;
        sW[d * WSTR + o] = W[idx];
    }
    #pragma unroll
    for (int i = 0; i < 32; i++) {
        int idx = tid + i * 256;
        int r = idx >> 6, d = idx & 63;
        int gr = row0 + r;
        sX[d * XSTR + r] = (gr < n) ? X[(size_t)gr * DDIM + d] : 0.0f;
    }
    __syncthreads();

    const int tx = tid & 15;
    const int ty = tid >> 4;
    const int o0 = tx * 4;
    const int r0 = ty * 8;

    unsigned long long accp[8][2];
    #pragma unroll
    for (int i = 0; i < 8; i++) {
        accp[i][0] = 0ULL;
        accp[i][1] = 0ULL;
    }

    #pragma unroll 16
    for (int d = 0; d < DDIM; d++) {
        float4 xa = *reinterpret_cast<const float4*>(&sX[d * XSTR + r0]);
        float4 xb = *reinterpret_cast<const float4*>(&sX[d * XSTR + r0 + 4]);
        ulonglong2 wp = *reinterpret_cast<const ulonglong2*>(&sW[d * WSTR + o0]);
        float x[8] = {xa.x, xa.y, xa.z, xa.w, xb.x, xb.y, xb.z, xb.w};
        #pragma unroll
        for (int i = 0; i < 8; i++) {
            unsigned xu = __float_as_uint(x[i]);
            unsigned long long xx;
            PACK_F32X2(xx, xu, xu);
            FMA_F32X2(accp[i][0], xx, wp.x);
            FMA_F32X2(accp[i][1], xx, wp.y);
        }
    }

    const float4 swv = *reinterpret_cast<const float4*>(&skipw[o0]);
    const float4 bvv = *reinterpret_cast<const float4*>(&bias[o0]);

    #pragma unroll
    for (int i = 0; i < 8; i++) {
        int gr = row0 + r0 + i;
        if (gr < n) {
            unsigned u0, u1, u2, u3;
            UNPACK_F32X2(u0, u1, accp[i][0]);
            UNPACK_F32X2(u2, u3, accp[i][1]);
            float4 hv = make_float4(__uint_as_float(u0), __uint_as_float(u1),
                                    __uint_as_float(u2), __uint_as_float(u3));
            __half2* dst2 = reinterpret_cast<__half2*>(&g_hh[(size_t)gr * DDIM + o0]);
            dst2[0] = __float22half2_rn(make_float2(hv.x, hv.y));
            dst2[1] = __float22half2_rn(make_float2(hv.z, hv.w));
            float4 ov;
            ov.x = fmaf(hv.x, swv.x, bvv.x);
            ov.y = fmaf(hv.y, swv.y, bvv.y);
            ov.z = fmaf(hv.z, swv.z, bvv.z);
            ov.w = fmaf(hv.w, swv.w, bvv.w);
            *reinterpret_cast<float4*>(&out[(size_t)gr * DDIM + o0]) = ov;
        }
    }
}

// ---------------------------------------------------------------------------
// Kernel 2: out[dst] += h_fp16[src] * w   via red.global.add.v4.f32
// Software-pipelined: issue 8 independent gather LDGs FIRST, then 8 reds —
// the red's "memory" clobber can no longer fence subsequent loads behind it.
// ---------------------------------------------------------------------------
#define EPB 256

__global__ void __launch_bounds__(256) scatter_kernel(
    const float* __restrict__ ew,
    const int*   __restrict__ src,
    const int*   __restrict__ dst,
    float* __restrict__ out,
    int E)
{
    __shared__ int   es[EPB];
    __shared__ int   ed[EPB];
    __shared__ float ewt[EPB];

    const int tid  = threadIdx.x;
    const int base = blockIdx.x * EPB;

    int ge = base + tid;
    if (ge < E) {
        es[tid]  = src[ge];
        ed[tid]  = dst[ge];
        ewt[tid] = ew[ge];
    }
    __syncthreads();

    const int lane4 = (tid & 15) << 2;   // 0,4,...,60
    const int esub  = tid >> 4;          // 0..15

    #pragma unroll
    for (int b = 0; b < 2; b++) {
        uint2 pk[8];
        int   dd[8];
        float ww[8];

        // Phase 1: 8 independent gathers (+meta), no red in between -> MLP 8
        #pragma unroll
        for (int q = 0; q < 8; q++) {
            int e = (b * 8 + q) * 16 + esub;
            bool ok = (base + e) < E;
            int s  = ok ? es[e] : 0;       // row 0 is always a safe address
            dd[q]  = ok ? ed[e] : -1;
            ww[q]  = ok ? ewt[e] : 0.0f;
            pk[q] = *reinterpret_cast<const uint2*>(
                &g_hh[(size_t)s * DDIM + lane4]);
        }

        // Phase 2: 8 fire-and-forget reductions
        #pragma unroll
        for (int q = 0; q < 8; q++) {
            if (dd[q] < 0) continue;
            float2 f0 = __half22float2(*reinterpret_cast<const __half2*>(&pk[q].x));
            float2 f1 = __half22float2(*reinterpret_cast<const __half2*>(&pk[q].y));
            float w = ww[q];
            float* o = out + (size_t)dd[q] * DDIM + lane4;
            asm volatile(
                "red.global.add.v4.f32 [%0], {%1, %2, %3, %4};"
                :: "l"(o), "f"(f0.x * w), "f"(f0.y * w), "f"(f1.x * w), "f"(f1.y * w)
                : "memory");
        }
    }
}

// ---------------------------------------------------------------------------
// Kernel 3: in-place SELU
// ---------------------------------------------------------------------------
__global__ void __launch_bounds__(256) selu_kernel(float* __restrict__ out, int total4)
{
    const float scale = 1.0507009873554805f;
    const float alpha = 1.6732632423543772f;
    int i = blockIdx.x * blockDim.x + threadIdx.x;
    if (i >= total4) return;
    float4 v = reinterpret_cast<float4*>(out)[i];
    v.x = v.x > 0.0f ? scale * v.x : scale * alpha * (expf(v.x) - 1.0f);
    v.y = v.y > 0.0f ? scale * v.y : scale * alpha * (expf(v.y) - 1.0f);
    v.z = v.z > 0.0f ? scale * v.z : scale * alpha * (expf(v.z) - 1.0f);
    v.w = v.w > 0.0f ? scale * v.w : scale * alpha * (expf(v.w) - 1.0f);
    reinterpret_cast<float4*>(out)[i] = v;
}

extern "C" void kernel_launch(void* const* d_in, const int* in_sizes, int n_in,
                              void* d_out, int out_size)
{
    const float* features = (const float*)d_in[0];
    const float* W        = (const float*)d_in[1];
    const float* bias     = (const float*)d_in[2];
    const float* skipw    = (const float*)d_in[3];
    const float* ew       = (const float*)d_in[4];
    const int*   esrc     = (const int*)d_in[5];
    const int*   edst     = (const int*)d_in[6];
    float* out = (float*)d_out;

    const int n = in_sizes[0] / DDIM;     // 50000
    const int E = in_sizes[4];            // 800000

    // 1. GEMM + skip/bias accumulator init + fp16 copy
    gemm_skip_kernel<<<(n + 127) / 128, 256>>>(features, W, bias, skipw, out, n);

    // 2. edge-parallel scatter (16 threads/edge, staged meta, pipelined loads)
    int sblocks = (E + EPB - 1) / EPB;
    scatter_kernel<<<sblocks, 256>>>(ew, esrc, edst, out, E);

    // 3. SELU in place
    int total4 = (n * DDIM) / 4;
    selu_kernel<<<(total4 + 255) / 256, 256>>>(out, total4);
}